// round 5
// baseline (speedup 1.0000x reference)
#include <cuda_runtime.h>
#include <cstdint>

#define Bsz 512
#define Nn  8192

// Scratch (static __device__ per harness rules)
__device__ float4 g_lplq4[(size_t)Bsz * Nn / 2]; // pair k: (lp2k,lq2k,lp2k+1,lq2k+1), [k][b]
__device__ float  g_r    [(size_t)Bsz * Nn];     // r_i = x1_i - A1_i, layout [b][i]
__device__ int    g_sel  [Bsz];

__device__ __forceinline__ float neg_inf_f() { return __int_as_float(0xff800000); }

// log1mexp(x) = log(1 - e^x), x <= 0, matching the reference's branch structure
__device__ __forceinline__ float log1mexp_f(float x) {
    return (x > -0.69314718f) ? logf(-expm1f(x)) : log1pf(-expf(x));
}

// One DP step, byte-identical op order to the R1-R4 kernels (bit-exact)
#define STEP(A0, A1, lp, lq, rv) do {                      \
    const float x1_ = (A0) + (lp);                         \
    const float x2_ = (A1) + (lq);                         \
    const float m_  = fmaxf(x1_, x2_);                     \
    const float dd_ = x1_ - x2_;                           \
    const float t_  = log1pf(expf(-fabsf(dd_)));           \
    (A1) = m_ + t_;                                        \
    (A0) = (A0) + (lq);                                    \
    (rv) = x1_ - (A1);                                     \
} while (0)

// ---------------------------------------------------------------------------
// Kernel 1: elementwise lp/lq from logits, pair-packed float4, [pair][b]
// ---------------------------------------------------------------------------
__global__ void k_prep(const float* __restrict__ logits) {
    __shared__ float2 tile[32][33];
    const int tx = threadIdx.x, ty = threadIdx.y;
    const int i0 = blockIdx.x * 32;   // item index base
    const int b0 = blockIdx.y * 32;   // row index base

    #pragma unroll
    for (int r = 0; r < 4; r++) {
        const int b = b0 + ty + r * 8;
        const int i = i0 + tx;
        const float z = logits[(size_t)b * Nn + i];
        // jax.nn.log_sigmoid(z) = -(max(-z,0) + log1p(exp(-|z|)))
        const float sp = fmaxf(-z, 0.0f) + log1pf(expf(-fabsf(z)));
        const float lp = fminf(-sp, -1e-7f);
        const float lq = log1mexp_f(lp);
        tile[ty + r * 8][tx] = make_float2(lp, lq);
    }
    __syncthreads();
    // write pair-packed: pair m within tile (0..15), row tx
    #pragma unroll
    for (int r = 0; r < 2; r++) {
        const int m = r * 8 + ty;
        const int b = b0 + tx;
        const float2 e0 = tile[tx][2 * m];
        const float2 e1 = tile[tx][2 * m + 1];
        g_lplq4[(size_t)(i0 / 2 + m) * Bsz + b] = make_float4(e0.x, e0.y, e1.x, e1.y);
    }
}

// reset g_sel each launch (graph replays must be deterministic)
__global__ void k_reset() { g_sel[threadIdx.x] = -1; }
__global__ void k_pad() {}   // keeps k_scan at ncu's captured launch slot

// ---------------------------------------------------------------------------
// Kernel 2: sequential forward DP, TWO independent rows per thread (ILP=2).
// Chain-B instructions fill chain-A's expf/log1pf stall shadows.
// 8 blocks x 32 lanes: lane handles rows b and b+256.
// ---------------------------------------------------------------------------
__global__ void __launch_bounds__(32, 1) k_scan() {
    const int lane = threadIdx.x;
    const int ba = blockIdx.x * 32 + lane;   // rows 0..255
    const int bb = ba + 256;                 // rows 256..511

    float A0a = 0.0f, A1a = neg_inf_f();
    float A0b = 0.0f, A1b = neg_inf_f();
    float4* __restrict__ ra = (float4*)(g_r + (size_t)ba * Nn);
    float4* __restrict__ rb = (float4*)(g_r + (size_t)bb * Nn);

    // chunk = 8 items = 4 packed float4 pairs; double buffered
    float4 bufa[2][4], bufb[2][4];
    #pragma unroll
    for (int j = 0; j < 4; j++) {
        bufa[0][j] = g_lplq4[(size_t)j * Bsz + ba];
        bufb[0][j] = g_lplq4[(size_t)j * Bsz + bb];
    }
    #pragma unroll
    for (int j = 0; j < 4; j++) {
        bufa[1][j] = g_lplq4[(size_t)(4 + j) * Bsz + ba];
        bufb[1][j] = g_lplq4[(size_t)(4 + j) * Bsz + bb];
    }

    const int NCHUNK = Nn / 8;   // 1024
    for (int c = 0; c < NCHUNK; c++) {
        const int ph = c & 1;
        float4 aca, acb;
        #pragma unroll
        for (int jj = 0; jj < 4; jj++) {
            const float4 va = bufa[ph][jj];
            const float4 vb = bufb[ph][jj];
            float rva0, rvb0, rva1, rvb1;
            STEP(A0a, A1a, va.x, va.y, rva0);
            STEP(A0b, A1b, vb.x, vb.y, rvb0);
            STEP(A0a, A1a, va.z, va.w, rva1);
            STEP(A0b, A1b, vb.z, vb.w, rvb1);
            if (jj == 0)      { aca.x = rva0; aca.y = rva1; acb.x = rvb0; acb.y = rvb1; }
            else if (jj == 1) { aca.z = rva0; aca.w = rva1; acb.z = rvb0; acb.w = rvb1;
                                ra[c * 2] = aca; rb[c * 2] = acb; }
            else if (jj == 2) { aca.x = rva0; aca.y = rva1; acb.x = rvb0; acb.y = rvb1; }
            else              { aca.z = rva0; aca.w = rva1; acb.z = rvb0; acb.w = rvb1;
                                ra[c * 2 + 1] = aca; rb[c * 2 + 1] = acb; }
        }
        if (c + 2 < NCHUNK) {
            const size_t base = (size_t)(4 * (c + 2)) * Bsz;
            #pragma unroll
            for (int j = 0; j < 4; j++) {
                bufa[ph][j] = g_lplq4[base + (size_t)j * Bsz + ba];
                bufb[ph][j] = g_lplq4[base + (size_t)j * Bsz + bb];
            }
        }
    }
}

// ---------------------------------------------------------------------------
// Kernel 3: parallel decisions. With K=1, selected item = MAX index i with
// u_i < sigmoid(p_i - q_i) (thresholds after the success are exactly 0).
// ---------------------------------------------------------------------------
__global__ void k_decide(const float* __restrict__ noise) {
    const int e  = blockIdx.x * blockDim.x + threadIdx.x;   // over Bsz*Nn/4
    const int b  = e >> 11;                                  // 2048 float4 per row
    const int i0 = (e & 2047) * 4;
    const float4 rv = ((const float4*)g_r)[e];
    const float4 uv = ((const float4*)noise)[e];

    int sel = -1;
    #pragma unroll
    for (int j = 0; j < 4; j++) {
        float r = (j == 0) ? rv.x : (j == 1) ? rv.y : (j == 2) ? rv.z : rv.w;
        const float u = (j == 0) ? uv.x : (j == 1) ? uv.y : (j == 2) ? uv.z : uv.w;
        r = fminf(r, 0.0f);                       // clamp, ref op order
        const float q = log1mexp_f(r);
        const float d = r - q;
        const float t = 1.0f / (1.0f + expf(-d)); // sigmoid; d=+inf -> 1
        if (u < t) sel = i0 + j;
    }
    #pragma unroll
    for (int s = 16; s > 0; s >>= 1)
        sel = max(sel, __shfl_xor_sync(0xffffffffu, sel, s));
    if ((threadIdx.x & 31) == 0 && sel >= 0) atomicMax(&g_sel[b], sel);
}

// ---------------------------------------------------------------------------
// Kernel 4: write output (one 1 per row at the selected index, else 0), f4
// ---------------------------------------------------------------------------
__global__ void k_write(float4* __restrict__ out) {
    const int e = blockIdx.x * blockDim.x + threadIdx.x;   // over Bsz*Nn/4
    const int b = e >> 11;
    const int i = (e & 2047) * 4;
    const int s = g_sel[b];
    float4 v;
    v.x = (i     == s) ? 1.0f : 0.0f;
    v.y = (i + 1 == s) ? 1.0f : 0.0f;
    v.z = (i + 2 == s) ? 1.0f : 0.0f;
    v.w = (i + 3 == s) ? 1.0f : 0.0f;
    out[e] = v;
}

extern "C" void kernel_launch(void* const* d_in, const int* in_sizes, int n_in,
                              void* d_out, int out_size) {
    const float* logits = (const float*)d_in[0];
    const float* noise  = (const float*)d_in[1];
    float4* out = (float4*)d_out;

    dim3 b1(32, 8), g1(Nn / 32, Bsz / 32);
    k_prep<<<g1, b1>>>(logits);
    k_reset<<<1, Bsz>>>();
    k_pad<<<1, 32>>>();                              // k_scan -> ncu slot #6
    k_scan<<<8, 32>>>();
    k_decide<<<(Bsz * Nn / 4) / 256, 256>>>(noise);
    k_write<<<(Bsz * Nn / 4) / 256, 256>>>(out);
}

// round 6
// speedup vs baseline: 1.3616x; 1.3616x over previous
#include <cuda_runtime.h>
#include <cstdint>

#define Bsz 512
#define Nn  8192

// Scratch (static __device__ per harness rules)
__device__ float4 g_lplq4[(size_t)Bsz * Nn / 2]; // pair k: (lp2k,lq2k,lp2k+1,lq2k+1), [k][b]
__device__ float  g_r    [(size_t)Bsz * Nn];     // r_i = x1_i - A1_i, layout [b][i]
__device__ int    g_sel  [Bsz];

__device__ __forceinline__ float neg_inf_f() { return __int_as_float(0xff800000); }

// log1mexp(x) = log(1 - e^x), x <= 0, matching the reference's branch structure
__device__ __forceinline__ float log1mexp_f(float x) {
    return (x > -0.69314718f) ? logf(-expm1f(x)) : log1pf(-expf(x));
}

// One DP step, byte-identical op order to the R1-R4 kernels (bit-exact)
#define STEP(A0, A1, lp, lq, rv) do {                      \
    const float x1_ = (A0) + (lp);                         \
    const float x2_ = (A1) + (lq);                         \
    const float m_  = fmaxf(x1_, x2_);                     \
    const float dd_ = x1_ - x2_;                           \
    const float t_  = log1pf(expf(-fabsf(dd_)));           \
    (A1) = m_ + t_;                                        \
    (A0) = (A0) + (lq);                                    \
    (rv) = x1_ - (A1);                                     \
} while (0)

// ---------------------------------------------------------------------------
// Kernel 1: elementwise lp/lq from logits, pair-packed float4, [pair][b]
// ---------------------------------------------------------------------------
__global__ void k_prep(const float* __restrict__ logits) {
    __shared__ float2 tile[32][33];
    const int tx = threadIdx.x, ty = threadIdx.y;
    const int i0 = blockIdx.x * 32;   // item index base
    const int b0 = blockIdx.y * 32;   // row index base

    #pragma unroll
    for (int r = 0; r < 4; r++) {
        const int b = b0 + ty + r * 8;
        const int i = i0 + tx;
        const float z = logits[(size_t)b * Nn + i];
        // jax.nn.log_sigmoid(z) = -(max(-z,0) + log1p(exp(-|z|)))
        const float sp = fmaxf(-z, 0.0f) + log1pf(expf(-fabsf(z)));
        const float lp = fminf(-sp, -1e-7f);
        const float lq = log1mexp_f(lp);
        tile[ty + r * 8][tx] = make_float2(lp, lq);
    }
    __syncthreads();
    // write pair-packed: pair m within tile (0..15), row tx
    #pragma unroll
    for (int r = 0; r < 2; r++) {
        const int m = r * 8 + ty;
        const int b = b0 + tx;
        const float2 e0 = tile[tx][2 * m];
        const float2 e1 = tile[tx][2 * m + 1];
        g_lplq4[(size_t)(i0 / 2 + m) * Bsz + b] = make_float4(e0.x, e0.y, e1.x, e1.y);
    }
}

// reset g_sel each launch (graph replays must be deterministic)
__global__ void k_reset() { g_sel[threadIdx.x] = -1; }
__global__ void k_pad() {}   // keeps k_scan at ncu's captured launch slot

// ---------------------------------------------------------------------------
// Kernel 2: sequential forward DP, TWO independent rows per thread (ILP=2),
// explicit A/B double buffers with compile-time indexing ONLY (the R5 version
// used a runtime-indexed buffer array -> local-memory demotion -> 35cy
// LDL/STL on the chain's in-order issue stream).
// 8 blocks x 32 lanes: lane handles rows b and b+256.
// Chunk = 8 items = 4 packed float4 pairs per chain; double buffered.
// ---------------------------------------------------------------------------
__global__ void __launch_bounds__(32, 1) k_scan() {
    const int lane = threadIdx.x;
    const int ba = blockIdx.x * 32 + lane;   // rows 0..255
    const int bb = ba + 256;                 // rows 256..511

    float A0a = 0.0f, A1a = neg_inf_f();
    float A0b = 0.0f, A1b = neg_inf_f();
    float4* __restrict__ ra = (float4*)(g_r + (size_t)ba * Nn);
    float4* __restrict__ rb = (float4*)(g_r + (size_t)bb * Nn);

    float4 aA[4], aB[4];   // chain a: buffers for chunk c (A) and c+1 (B)
    float4 bA[4], bB[4];   // chain b

    #pragma unroll
    for (int j = 0; j < 4; j++) {
        aA[j] = g_lplq4[(size_t)j * Bsz + ba];
        bA[j] = g_lplq4[(size_t)j * Bsz + bb];
    }
    #pragma unroll
    for (int j = 0; j < 4; j++) {
        aB[j] = g_lplq4[(size_t)(4 + j) * Bsz + ba];
        bB[j] = g_lplq4[(size_t)(4 + j) * Bsz + bb];
    }

    const int NCHUNK = Nn / 8;   // 1024
    for (int c = 0; c < NCHUNK; c += 2) {
        // ---- chunk c: consume A buffers ----
        {
            float4 aca, acb;
            #pragma unroll
            for (int jj = 0; jj < 4; jj++) {
                const float4 va = aA[jj];
                const float4 vb = bA[jj];
                float rva0, rvb0, rva1, rvb1;
                STEP(A0a, A1a, va.x, va.y, rva0);
                STEP(A0b, A1b, vb.x, vb.y, rvb0);
                STEP(A0a, A1a, va.z, va.w, rva1);
                STEP(A0b, A1b, vb.z, vb.w, rvb1);
                if (jj == 0)      { aca.x = rva0; aca.y = rva1; acb.x = rvb0; acb.y = rvb1; }
                else if (jj == 1) { aca.z = rva0; aca.w = rva1; acb.z = rvb0; acb.w = rvb1;
                                    ra[c * 2] = aca; rb[c * 2] = acb; }
                else if (jj == 2) { aca.x = rva0; aca.y = rva1; acb.x = rvb0; acb.y = rvb1; }
                else              { aca.z = rva0; aca.w = rva1; acb.z = rvb0; acb.w = rvb1;
                                    ra[c * 2 + 1] = aca; rb[c * 2 + 1] = acb; }
            }
        }
        if (c + 2 < NCHUNK) {
            const size_t base = (size_t)(4 * (c + 2)) * Bsz;
            #pragma unroll
            for (int j = 0; j < 4; j++) {
                aA[j] = g_lplq4[base + (size_t)j * Bsz + ba];
                bA[j] = g_lplq4[base + (size_t)j * Bsz + bb];
            }
        }
        // ---- chunk c+1: consume B buffers ----
        {
            float4 aca, acb;
            #pragma unroll
            for (int jj = 0; jj < 4; jj++) {
                const float4 va = aB[jj];
                const float4 vb = bB[jj];
                float rva0, rvb0, rva1, rvb1;
                STEP(A0a, A1a, va.x, va.y, rva0);
                STEP(A0b, A1b, vb.x, vb.y, rvb0);
                STEP(A0a, A1a, va.z, va.w, rva1);
                STEP(A0b, A1b, vb.z, vb.w, rvb1);
                if (jj == 0)      { aca.x = rva0; aca.y = rva1; acb.x = rvb0; acb.y = rvb1; }
                else if (jj == 1) { aca.z = rva0; aca.w = rva1; acb.z = rvb0; acb.w = rvb1;
                                    ra[(c + 1) * 2] = aca; rb[(c + 1) * 2] = acb; }
                else if (jj == 2) { aca.x = rva0; aca.y = rva1; acb.x = rvb0; acb.y = rvb1; }
                else              { aca.z = rva0; aca.w = rva1; acb.z = rvb0; acb.w = rvb1;
                                    ra[(c + 1) * 2 + 1] = aca; rb[(c + 1) * 2 + 1] = acb; }
            }
        }
        if (c + 3 < NCHUNK) {
            const size_t base = (size_t)(4 * (c + 3)) * Bsz;
            #pragma unroll
            for (int j = 0; j < 4; j++) {
                aB[j] = g_lplq4[base + (size_t)j * Bsz + ba];
                bB[j] = g_lplq4[base + (size_t)j * Bsz + bb];
            }
        }
    }
}

// ---------------------------------------------------------------------------
// Kernel 3: parallel decisions. With K=1, selected item = MAX index i with
// u_i < sigmoid(p_i - q_i) (thresholds after the success are exactly 0).
// ---------------------------------------------------------------------------
__global__ void k_decide(const float* __restrict__ noise) {
    const int e  = blockIdx.x * blockDim.x + threadIdx.x;   // over Bsz*Nn/4
    const int b  = e >> 11;                                  // 2048 float4 per row
    const int i0 = (e & 2047) * 4;
    const float4 rv = ((const float4*)g_r)[e];
    const float4 uv = ((const float4*)noise)[e];

    int sel = -1;
    #pragma unroll
    for (int j = 0; j < 4; j++) {
        float r = (j == 0) ? rv.x : (j == 1) ? rv.y : (j == 2) ? rv.z : rv.w;
        const float u = (j == 0) ? uv.x : (j == 1) ? uv.y : (j == 2) ? uv.z : uv.w;
        r = fminf(r, 0.0f);                       // clamp, ref op order
        const float q = log1mexp_f(r);
        const float d = r - q;
        const float t = 1.0f / (1.0f + expf(-d)); // sigmoid; d=+inf -> 1
        if (u < t) sel = i0 + j;
    }
    #pragma unroll
    for (int s = 16; s > 0; s >>= 1)
        sel = max(sel, __shfl_xor_sync(0xffffffffu, sel, s));
    if ((threadIdx.x & 31) == 0 && sel >= 0) atomicMax(&g_sel[b], sel);
}

// ---------------------------------------------------------------------------
// Kernel 4: write output (one 1 per row at the selected index, else 0), f4
// ---------------------------------------------------------------------------
__global__ void k_write(float4* __restrict__ out) {
    const int e = blockIdx.x * blockDim.x + threadIdx.x;   // over Bsz*Nn/4
    const int b = e >> 11;
    const int i = (e & 2047) * 4;
    const int s = g_sel[b];
    float4 v;
    v.x = (i     == s) ? 1.0f : 0.0f;
    v.y = (i + 1 == s) ? 1.0f : 0.0f;
    v.z = (i + 2 == s) ? 1.0f : 0.0f;
    v.w = (i + 3 == s) ? 1.0f : 0.0f;
    out[e] = v;
}

extern "C" void kernel_launch(void* const* d_in, const int* in_sizes, int n_in,
                              void* d_out, int out_size) {
    const float* logits = (const float*)d_in[0];
    const float* noise  = (const float*)d_in[1];
    float4* out = (float4*)d_out;

    dim3 b1(32, 8), g1(Nn / 32, Bsz / 32);
    k_prep<<<g1, b1>>>(logits);
    k_reset<<<1, Bsz>>>();
    k_pad<<<1, 32>>>();                              // k_scan -> ncu slot #6
    k_scan<<<8, 32>>>();
    k_decide<<<(Bsz * Nn / 4) / 256, 256>>>(noise);
    k_write<<<(Bsz * Nn / 4) / 256, 256>>>(out);
}

// round 7
// speedup vs baseline: 1.4278x; 1.0487x over previous
#include <cuda_runtime.h>
#include <cstdint>

#define Bsz 512
#define Nn  8192

// Scratch (static __device__ per harness rules)
__device__ float4 g_lplq4[(size_t)Bsz * Nn / 2]; // pair k: (lp2k,lq2k,lp2k+1,lq2k+1), [k][b]
__device__ float  g_r    [(size_t)Bsz * Nn];     // r_i = x1_i - A1_i, layout [b][i]
__device__ int    g_sel  [Bsz];

__device__ __forceinline__ float neg_inf_f() { return __int_as_float(0xff800000); }

// log1mexp(x) = log(1 - e^x), x <= 0, matching the reference's branch structure
__device__ __forceinline__ float log1mexp_f(float x) {
    return (x > -0.69314718f) ? logf(-expm1f(x)) : log1pf(-expf(x));
}

// One DP step, byte-identical op order to the R1-R6 kernels (bit-exact)
#define STEP(A0, A1, lp, lq, rv) do {                      \
    const float x1_ = (A0) + (lp);                         \
    const float x2_ = (A1) + (lq);                         \
    const float m_  = fmaxf(x1_, x2_);                     \
    const float dd_ = x1_ - x2_;                           \
    const float t_  = log1pf(expf(-fabsf(dd_)));           \
    (A1) = m_ + t_;                                        \
    (A0) = (A0) + (lq);                                    \
    (rv) = x1_ - (A1);                                     \
} while (0)

// ---------------------------------------------------------------------------
// Kernel 1: elementwise lp/lq from logits, pair-packed float4, [pair][b]
// ---------------------------------------------------------------------------
__global__ void k_prep(const float* __restrict__ logits) {
    __shared__ float2 tile[32][33];
    const int tx = threadIdx.x, ty = threadIdx.y;
    const int i0 = blockIdx.x * 32;   // item index base
    const int b0 = blockIdx.y * 32;   // row index base

    #pragma unroll
    for (int r = 0; r < 4; r++) {
        const int b = b0 + ty + r * 8;
        const int i = i0 + tx;
        const float z = logits[(size_t)b * Nn + i];
        // jax.nn.log_sigmoid(z) = -(max(-z,0) + log1p(exp(-|z|)))
        const float sp = fmaxf(-z, 0.0f) + log1pf(expf(-fabsf(z)));
        const float lp = fminf(-sp, -1e-7f);
        const float lq = log1mexp_f(lp);
        tile[ty + r * 8][tx] = make_float2(lp, lq);
    }
    __syncthreads();
    // write pair-packed: pair m within tile (0..15), row tx
    #pragma unroll
    for (int r = 0; r < 2; r++) {
        const int m = r * 8 + ty;
        const int b = b0 + tx;
        const float2 e0 = tile[tx][2 * m];
        const float2 e1 = tile[tx][2 * m + 1];
        g_lplq4[(size_t)(i0 / 2 + m) * Bsz + b] = make_float4(e0.x, e0.y, e1.x, e1.y);
    }
}

// reset g_sel each launch (graph replays must be deterministic)
__global__ void k_reset() { g_sel[threadIdx.x] = -1; }
__global__ void k_pad() {}   // keeps k_scan at ncu's captured launch slot

// ---------------------------------------------------------------------------
// Kernel 2: sequential forward DP, ONE row per thread, but 2 WARPS PER SMSP:
// 2 blocks x 256 threads -> warps 0..7 map to SMSPs 0..3 twice (wid % 4).
// While one warp stalls on its expf/log1pf chain, the co-resident warp
// issues -- dynamic TLP, immune to the branch barriers that defeated
// compile-time ILP in R5/R6. Per-row FP op order unchanged (bit-exact).
// ---------------------------------------------------------------------------
__global__ void __launch_bounds__(256, 1) k_scan() {
    const int b = blockIdx.x * 256 + threadIdx.x;   // one row per thread
    float4* __restrict__ rrow = (float4*)(g_r + (size_t)b * Nn);

    float A0 = 0.0f, A1 = neg_inf_f();

    // chunk = 8 items = 4 pair-packed float4; double buffered, names only
    float4 bufA[4], bufB[4];
    #pragma unroll
    for (int j = 0; j < 4; j++) bufA[j] = g_lplq4[(size_t)j * Bsz + b];
    #pragma unroll
    for (int j = 0; j < 4; j++) bufB[j] = g_lplq4[(size_t)(4 + j) * Bsz + b];

    const int NCHUNK = Nn / 8;   // 1024
    for (int c = 0; c < NCHUNK; c += 2) {
        // ---- chunk c: consume bufA ----
        {
            float4 acc;
            #pragma unroll
            for (int jj = 0; jj < 4; jj++) {
                const float4 v = bufA[jj];
                float r0, r1;
                STEP(A0, A1, v.x, v.y, r0);
                STEP(A0, A1, v.z, v.w, r1);
                if (jj == 0)      { acc.x = r0; acc.y = r1; }
                else if (jj == 1) { acc.z = r0; acc.w = r1; rrow[c * 2] = acc; }
                else if (jj == 2) { acc.x = r0; acc.y = r1; }
                else              { acc.z = r0; acc.w = r1; rrow[c * 2 + 1] = acc; }
            }
        }
        if (c + 2 < NCHUNK) {
            const size_t base = (size_t)(4 * (c + 2)) * Bsz;
            #pragma unroll
            for (int j = 0; j < 4; j++) bufA[j] = g_lplq4[base + (size_t)j * Bsz + b];
        }
        // ---- chunk c+1: consume bufB ----
        {
            float4 acc;
            #pragma unroll
            for (int jj = 0; jj < 4; jj++) {
                const float4 v = bufB[jj];
                float r0, r1;
                STEP(A0, A1, v.x, v.y, r0);
                STEP(A0, A1, v.z, v.w, r1);
                if (jj == 0)      { acc.x = r0; acc.y = r1; }
                else if (jj == 1) { acc.z = r0; acc.w = r1; rrow[(c + 1) * 2] = acc; }
                else if (jj == 2) { acc.x = r0; acc.y = r1; }
                else              { acc.z = r0; acc.w = r1; rrow[(c + 1) * 2 + 1] = acc; }
            }
        }
        if (c + 3 < NCHUNK) {
            const size_t base = (size_t)(4 * (c + 3)) * Bsz;
            #pragma unroll
            for (int j = 0; j < 4; j++) bufB[j] = g_lplq4[base + (size_t)j * Bsz + b];
        }
    }
}

// ---------------------------------------------------------------------------
// Kernel 3: parallel decisions. With K=1, selected item = MAX index i with
// u_i < sigmoid(p_i - q_i) (thresholds after the success are exactly 0).
// ---------------------------------------------------------------------------
__global__ void k_decide(const float* __restrict__ noise) {
    const int e  = blockIdx.x * blockDim.x + threadIdx.x;   // over Bsz*Nn/4
    const int b  = e >> 11;                                  // 2048 float4 per row
    const int i0 = (e & 2047) * 4;
    const float4 rv = ((const float4*)g_r)[e];
    const float4 uv = ((const float4*)noise)[e];

    int sel = -1;
    #pragma unroll
    for (int j = 0; j < 4; j++) {
        float r = (j == 0) ? rv.x : (j == 1) ? rv.y : (j == 2) ? rv.z : rv.w;
        const float u = (j == 0) ? uv.x : (j == 1) ? uv.y : (j == 2) ? uv.z : uv.w;
        r = fminf(r, 0.0f);                       // clamp, ref op order
        const float q = log1mexp_f(r);
        const float d = r - q;
        const float t = 1.0f / (1.0f + expf(-d)); // sigmoid; d=+inf -> 1
        if (u < t) sel = i0 + j;
    }
    #pragma unroll
    for (int s = 16; s > 0; s >>= 1)
        sel = max(sel, __shfl_xor_sync(0xffffffffu, sel, s));
    if ((threadIdx.x & 31) == 0 && sel >= 0) atomicMax(&g_sel[b], sel);
}

// ---------------------------------------------------------------------------
// Kernel 4: write output (one 1 per row at the selected index, else 0), f4
// ---------------------------------------------------------------------------
__global__ void k_write(float4* __restrict__ out) {
    const int e = blockIdx.x * blockDim.x + threadIdx.x;   // over Bsz*Nn/4
    const int b = e >> 11;
    const int i = (e & 2047) * 4;
    const int s = g_sel[b];
    float4 v;
    v.x = (i     == s) ? 1.0f : 0.0f;
    v.y = (i + 1 == s) ? 1.0f : 0.0f;
    v.z = (i + 2 == s) ? 1.0f : 0.0f;
    v.w = (i + 3 == s) ? 1.0f : 0.0f;
    out[e] = v;
}

extern "C" void kernel_launch(void* const* d_in, const int* in_sizes, int n_in,
                              void* d_out, int out_size) {
    const float* logits = (const float*)d_in[0];
    const float* noise  = (const float*)d_in[1];
    float4* out = (float4*)d_out;

    dim3 b1(32, 8), g1(Nn / 32, Bsz / 32);
    k_prep<<<g1, b1>>>(logits);
    k_reset<<<1, Bsz>>>();
    k_pad<<<1, 32>>>();                              // k_scan -> ncu slot #6
    k_scan<<<2, 256>>>();                            // 2 warps per SMSP (TLP)
    k_decide<<<(Bsz * Nn / 4) / 256, 256>>>(noise);
    k_write<<<(Bsz * Nn / 4) / 256, 256>>>(out);
}